// round 16
// baseline (speedup 1.0000x reference)
// R16: GEMMs re-partitioned to 4 warps x 64x64 tiles (128 threads) — halves
// fragment LDS duplication, same trick that won R15 for flash. Flash/prep
// unchanged from R15.
#include <cuda_runtime.h>
#include <cuda_fp16.h>
#include <math.h>
#include <stdint.h>

#define N_EMBD 1024
#define N_HEAD 16
#define HS 64
#define BATCH 4
#define SEQ 2048
#define MTOT (BATCH * SEQ)

__device__ __half g_xh[(size_t)MTOT * N_EMBD];
__device__ __half g_qkvh[(size_t)MTOT * 3 * N_EMBD];
__device__ __half g_yh[(size_t)MTOT * N_EMBD];
__device__ __half g_wta_h[(size_t)3 * N_EMBD * N_EMBD];
__device__ __half g_wtp_h[(size_t)N_EMBD * N_EMBD];

// ---------------------------------------------------------------------------
__device__ __forceinline__ void cp_async16(uint32_t dst, const void* src) {
    asm volatile("cp.async.cg.shared.global [%0], [%1], 16;" :: "r"(dst), "l"(src));
}
#define CP_COMMIT() asm volatile("cp.async.commit_group;" ::: "memory")
#define CP_WAIT0() asm volatile("cp.async.wait_group 0;" ::: "memory")
#define CP_WAIT1() asm volatile("cp.async.wait_group 1;" ::: "memory")

#define LDSM4(r0, r1, r2, r3, addr) \
    asm volatile("ldmatrix.sync.aligned.m8n8.x4.shared.b16 {%0,%1,%2,%3}, [%4];" \
                 : "=r"(r0), "=r"(r1), "=r"(r2), "=r"(r3) : "r"(addr))
#define LDSM4T(r0, r1, r2, r3, addr) \
    asm volatile("ldmatrix.sync.aligned.m8n8.x4.trans.shared.b16 {%0,%1,%2,%3}, [%4];" \
                 : "=r"(r0), "=r"(r1), "=r"(r2), "=r"(r3) : "r"(addr))

__device__ __forceinline__ void mma_f16(float* c, const uint32_t* a, const uint32_t* b) {
    asm volatile(
        "mma.sync.aligned.m16n8k16.row.col.f32.f16.f16.f32 "
        "{%0,%1,%2,%3}, {%4,%5,%6,%7}, {%8,%9}, {%0,%1,%2,%3};"
        : "+f"(c[0]), "+f"(c[1]), "+f"(c[2]), "+f"(c[3])
        : "r"(a[0]), "r"(a[1]), "r"(a[2]), "r"(a[3]), "r"(b[0]), "r"(b[1]));
}

__device__ __forceinline__ uint32_t pack_h2(float a, float b) {
    __half2 h = __floats2half2_rn(a, b);
    return *reinterpret_cast<uint32_t*>(&h);
}
__device__ __forceinline__ float ex2f(float x) {
    float r;
    asm("ex2.approx.f32 %0, %1;" : "=f"(r) : "f"(x));
    return r;
}
__device__ __forceinline__ uint32_t ex2_h2(uint32_t d) {
    uint32_t r;
    asm("ex2.approx.f16x2 %0, %1;" : "=r"(r) : "r"(d));
    return r;
}

// ---------------------------------------------------------------------------
__global__ __launch_bounds__(256) void cvt_half4(
    const float4* __restrict__ in, __half2* __restrict__ out, int n4)
{
    int i = blockIdx.x * blockDim.x + threadIdx.x;
    if (i < n4) {
        float4 v = in[i];
        out[2 * i] = __floats2half2_rn(v.x, v.y);
        out[2 * i + 1] = __floats2half2_rn(v.z, v.w);
    }
}

__global__ __launch_bounds__(256) void transpose_cvt(
    const float* __restrict__ in, __half* __restrict__ out, int R, int C)
{
    __shared__ float t[32][33];
    const int bx = blockIdx.x * 32, by = blockIdx.y * 32;
    const int tx = threadIdx.x & 31, ty = threadIdx.x >> 5;
    #pragma unroll
    for (int i = ty; i < 32; i += 8)
        t[i][tx] = in[(size_t)(by + i) * C + bx + tx];
    __syncthreads();
    #pragma unroll
    for (int i = ty; i < 32; i += 8)
        out[(size_t)(bx + i) * R + by + tx] = __float2half_rn(t[tx][i]);
}

// ---------------------------------------------------------------------------
// fp16 GEMM: 128x128 CTA tile, BK=64, 2-stage cp.async (R6 skeleton), but
// 128 threads / 4 warps as 2x2 grid with 64x64 warp tiles — A and B each
// read only 2x per chunk (was 4x/2x with 8 warps).
// ---------------------------------------------------------------------------
#define GEMM_SMEM 65536
#define QSCALE (0.125f * 1.4426950408889634f)

template <bool HALF_OUT>
__global__ __launch_bounds__(128, 2) void gemm_f16(
    const __half* __restrict__ A, const __half* __restrict__ Bt,
    void* __restrict__ Cv, int M, int N, int K, int scaleQ)
{
    extern __shared__ char smc[];
    const uint32_t sb = (uint32_t)__cvta_generic_to_shared(smc);
    const int tid = threadIdx.x, wid = tid >> 5, lane = tid & 31;
    const int gr = lane >> 2, gc = lane & 3;
    const int g8 = lane >> 3, r8 = lane & 7;
    const int wm = (wid & 1) * 64, wn = (wid >> 1) * 64;

    const __half* Ag = A + (size_t)blockIdx.y * 128 * K;
    const __half* Bg = Bt + (size_t)blockIdx.x * 128 * K;

    float acc[4][8][4];
    #pragma unroll
    for (int i = 0; i < 4; i++)
        #pragma unroll
        for (int j = 0; j < 8; j++)
            #pragma unroll
            for (int r = 0; r < 4; r++) acc[i][j][r] = 0.f;

    auto issue = [&](int c) {
        const int p = c & 1, k0 = c * 64;
        const uint32_t aB = sb + p * 32768, bB = aB + 16384;
        #pragma unroll
        for (int i = 0; i < 8; i++) {
            int u = tid + 128 * i, r = u >> 3, cu = u & 7;
            uint32_t d = (uint32_t)(r * 128 + ((cu ^ (r & 7)) << 4));
            cp_async16(aB + d, Ag + (size_t)r * K + k0 + cu * 8);
            cp_async16(bB + d, Bg + (size_t)r * K + k0 + cu * 8);
        }
        CP_COMMIT();
    };

    issue(0);
    const int NCH = K / 64;
    for (int c = 0; c < NCH; c++) {
        const int p = c & 1;
        if (c + 1 < NCH) { issue(c + 1); CP_WAIT1(); } else { CP_WAIT0(); }
        __syncthreads();
        const uint32_t aB = sb + p * 32768, bB = aB + 16384;

        #pragma unroll
        for (int ks = 0; ks < 4; ks++) {
            uint32_t a[4][4], b[8][2];
            #pragma unroll
            for (int i = 0; i < 4; i++) {
                int row = wm + i * 16 + (g8 & 1) * 8 + r8;
                int unit = 2 * ks + (g8 >> 1);
                LDSM4(a[i][0], a[i][1], a[i][2], a[i][3],
                      aB + row * 128 + ((unit ^ (row & 7)) << 4));
            }
            #pragma unroll
            for (int jp = 0; jp < 4; jp++) {
                int row = wn + jp * 16 + (g8 >> 1) * 8 + r8;
                int unit = 2 * ks + (g8 & 1);
                LDSM4(b[2 * jp][0], b[2 * jp][1], b[2 * jp + 1][0], b[2 * jp + 1][1],
                      bB + row * 128 + ((unit ^ (row & 7)) << 4));
            }
            #pragma unroll
            for (int i = 0; i < 4; i++)
                #pragma unroll
                for (int j = 0; j < 8; j++)
                    mma_f16(acc[i][j], a[i], b[j]);
        }
        __syncthreads();
    }

    const float sc = (scaleQ && blockIdx.x < 8) ? QSCALE : 1.0f;
    if (HALF_OUT) {
        __half* Ch = (__half*)Cv + (size_t)(blockIdx.y * 128 + wm) * N + blockIdx.x * 128 + wn;
        #pragma unroll
        for (int i = 0; i < 4; i++)
            #pragma unroll
            for (int j = 0; j < 8; j++) {
                *(__half2*)(Ch + (size_t)(i * 16 + gr) * N + j * 8 + 2 * gc) =
                    __floats2half2_rn(acc[i][j][0] * sc, acc[i][j][1] * sc);
                *(__half2*)(Ch + (size_t)(i * 16 + gr + 8) * N + j * 8 + 2 * gc) =
                    __floats2half2_rn(acc[i][j][2] * sc, acc[i][j][3] * sc);
            }
    } else {
        float* Cf = (float*)Cv + (size_t)(blockIdx.y * 128 + wm) * N + blockIdx.x * 128 + wn;
        #pragma unroll
        for (int i = 0; i < 4; i++)
            #pragma unroll
            for (int j = 0; j < 8; j++) {
                *(float2*)(Cf + (size_t)(i * 16 + gr) * N + j * 8 + 2 * gc) =
                    make_float2(acc[i][j][0], acc[i][j][1]);
                *(float2*)(Cf + (size_t)(i * 16 + gr + 8) * N + j * 8 + 2 * gc) =
                    make_float2(acc[i][j][2], acc[i][j][3]);
            }
    }
}

// ---------------------------------------------------------------------------
// fp16 flash attention (causal): unchanged from R15 (4 warps x 32 rows,
// exp2-domain f16x2 softmax, l via MMA row-sum).
// ---------------------------------------------------------------------------
#define FQ_OFF 0
#define FK_OFF 16384
#define FV_OFF (16384 + 3 * 8192)
#define FLASH_SMEM 65536
#define MASKF (-60000.0f)

__global__ __launch_bounds__(128, 2) void flash_f16(
    const __half* __restrict__ qkv, __half* __restrict__ y)
{
    extern __shared__ char smc[];
    const uint32_t sb = (uint32_t)__cvta_generic_to_shared(smc);
    const int qt = gridDim.x - 1 - blockIdx.x;
    const int b = blockIdx.y >> 4, h = blockIdx.y & 15;
    const int tid = threadIdx.x, wid = tid >> 5, lane = tid & 31;
    const int gr = lane >> 2, gc = lane & 3;
    const int g8 = lane >> 3, r8 = lane & 7;
    const int C3 = 3 * N_EMBD;
    const int q0 = qt * 128;
    const __half* gb = qkv + (size_t)(b * SEQ) * C3 + h * HS;
    const int jmax = 2 * qt + 1;
    const int wrow = q0 + wid * 32;

    auto issue_kv = [&](int j) {
        const int p3 = j % 3, kb = j * 64;
        #pragma unroll
        for (int i = 0; i < 4; i++) {
            int u = tid + 128 * i, r = u >> 3, cu = u & 7;
            uint32_t d = (uint32_t)(r * 128 + ((cu ^ (r & 7)) << 4)) + p3 * 8192;
            cp_async16(sb + FK_OFF + d, gb + N_EMBD + (size_t)(kb + r) * C3 + cu * 8);
            cp_async16(sb + FV_OFF + d, gb + 2 * N_EMBD + (size_t)(kb + r) * C3 + cu * 8);
        }
        CP_COMMIT();
    };

    {
        #pragma unroll
        for (int i = 0; i < 8; i++) {
            int u = tid + 128 * i, r = u >> 3, cu = u & 7;
            cp_async16(sb + FQ_OFF + r * 128 + ((cu ^ (r & 7)) << 4),
                       gb + (size_t)(q0 + r) * C3 + cu * 8);
        }
        #pragma unroll
        for (int i = 0; i < 4; i++) {
            int u = tid + 128 * i, r = u >> 3, cu = u & 7;
            uint32_t d = (uint32_t)(r * 128 + ((cu ^ (r & 7)) << 4));
            cp_async16(sb + FK_OFF + d, gb + N_EMBD + (size_t)r * C3 + cu * 8);
            cp_async16(sb + FV_OFF + d, gb + 2 * N_EMBD + (size_t)r * C3 + cu * 8);
        }
        CP_COMMIT();
        issue_kv(1);
    }

    uint32_t qa[4][2][4];
    float o[2][8][4];
    #pragma unroll
    for (int rb = 0; rb < 2; rb++)
        #pragma unroll
        for (int t = 0; t < 8; t++)
            #pragma unroll
            for (int r = 0; r < 4; r++) o[rb][t][r] = 0.f;
    float lrow[2][4] = {{0.f, 0.f, 0.f, 0.f}, {0.f, 0.f, 0.f, 0.f}};
    float m[4] = {-1e30f, -1e30f, -1e30f, -1e30f};
    const uint32_t onesb[2] = {0x3C003C00u, 0x3C003C00u};

    for (int j = 0; j <= jmax; j++) {
        if (j == jmax) { CP_WAIT0(); } else { CP_WAIT1(); }
        __syncthreads();
        if (j + 2 <= jmax) issue_kv(j + 2);

        if (j == 0) {
            #pragma unroll
            for (int ks = 0; ks < 4; ks++)
                #pragma unroll
                for (int rb = 0; rb < 2; rb++) {
                    int row = wid * 32 + rb * 16 + (g8 & 1) * 8 + r8;
                    int unit = 2 * ks + (g8 >> 1);
                    LDSM4(qa[ks][rb][0], qa[ks][rb][1], qa[ks][rb][2], qa[ks][rb][3],
                          sb + FQ_OFF + row * 128 + ((unit ^ (row & 7)) << 4));
                }
        }

        const int p3 = j % 3, kb = j * 64;
        if (kb <= wrow + 31) {
            const uint32_t Kb = sb + FK_OFF + p3 * 8192;
            float s[8][2][4];
            #pragma unroll
            for (int t = 0; t < 8; t++)
                #pragma unroll
                for (int rb = 0; rb < 2; rb++)
                    #pragma unroll
                    for (int r = 0; r < 4; r++) s[t][rb][r] = 0.f;
            #pragma unroll
            for (int t = 0; t < 8; t++) {
                uint32_t bfr[8];
                #pragma unroll
                for (int kp = 0; kp < 2; kp++) {
                    int row = 8 * t + r8;
                    int unit = 4 * kp + g8;
                    LDSM4(bfr[4 * kp], bfr[4 * kp + 1], bfr[4 * kp + 2], bfr[4 * kp + 3],
                          Kb + row * 128 + ((unit ^ (row & 7)) << 4));
                }
                #pragma unroll
                for (int ks = 0; ks < 4; ks++)
                    #pragma unroll
                    for (int rb = 0; rb < 2; rb++)
                        mma_f16(s[t][rb], qa[ks][rb], &bfr[2 * ks]);
            }
            float tm[4] = {-1e30f, -1e30f, -1e30f, -1e30f};
            if (kb + 63 < wrow) {
                #pragma unroll
                for (int t = 0; t < 8; t++)
                    #pragma unroll
                    for (int rb = 0; rb < 2; rb++) {
                        tm[2 * rb]     = fmaxf(tm[2 * rb], fmaxf(s[t][rb][0], s[t][rb][1]));
                        tm[2 * rb + 1] = fmaxf(tm[2 * rb + 1], fmaxf(s[t][rb][2], s[t][rb][3]));
                    }
            } else {
                #pragma unroll
                for (int t = 0; t < 8; t++) {
                    const int c0 = kb + 8 * t + 2 * gc, c1 = c0 + 1;
                    #pragma unroll
                    for (int rb = 0; rb < 2; rb++) {
                        const int rlo = wrow + rb * 16 + gr, rhi = rlo + 8;
                        s[t][rb][0] = (c0 <= rlo) ? s[t][rb][0] : MASKF;
                        s[t][rb][1] = (c1 <= rlo) ? s[t][rb][1] : MASKF;
                        s[t][rb][2] = (c0 <= rhi) ? s[t][rb][2] : MASKF;
                        s[t][rb][3] = (c1 <= rhi) ? s[t][rb][3] : MASKF;
                        tm[2 * rb]     = fmaxf(tm[2 * rb], fmaxf(s[t][rb][0], s[t][rb][1]));
                        tm[2 * rb + 1] = fmaxf(tm[2 * rb + 1], fmaxf(s[t][rb][2], s[t][rb][3]));
                    }
                }
            }
            #pragma unroll
            for (int k = 0; k < 4; k++)
                #pragma unroll
                for (int off = 1; off <= 2; off <<= 1)
                    tm[k] = fmaxf(tm[k], __shfl_xor_sync(0xffffffffu, tm[k], off));
            float mn[4], cf[4];
            #pragma unroll
            for (int k = 0; k < 4; k++) {
                mn[k] = fmaxf(m[k], tm[k]);
                cf[k] = ex2f(m[k] - mn[k]);
                m[k] = mn[k];
            }
            uint32_t pa[4][2][4];
            #pragma unroll
            for (int t = 0; t < 8; t++) {
                const int ks = t >> 1, hi = (t & 1) * 2;
                #pragma unroll
                for (int rb = 0; rb < 2; rb++) {
                    pa[ks][rb][hi]     = ex2_h2(pack_h2(s[t][rb][0] - mn[2 * rb],
                                                        s[t][rb][1] - mn[2 * rb]));
                    pa[ks][rb][hi + 1] = ex2_h2(pack_h2(s[t][rb][2] - mn[2 * rb + 1],
                                                        s[t][rb][3] - mn[2 * rb + 1]));
                }
            }
            #pragma unroll
            for (int rb = 0; rb < 2; rb++) {
                lrow[rb][0] *= cf[2 * rb];     lrow[rb][1] *= cf[2 * rb];
                lrow[rb][2] *= cf[2 * rb + 1]; lrow[rb][3] *= cf[2 * rb + 1];
                #pragma unroll
                for (int t = 0; t < 8; t++) {
                    o[rb][t][0] *= cf[2 * rb];     o[rb][t][1] *= cf[2 * rb];
                    o[rb][t][2] *= cf[2 * rb + 1]; o[rb][t][3] *= cf[2 * rb + 1];
                }
            }
            #pragma unroll
            for (int ks = 0; ks < 4; ks++)
                #pragma unroll
                for (int rb = 0; rb < 2; rb++)
                    mma_f16(lrow[rb], pa[ks][rb], onesb);
            const uint32_t Vb = sb + FV_OFF + p3 * 8192;
            #pragma unroll
            for (int tp = 0; tp < 4; tp++) {
                #pragma unroll
                for (int ks = 0; ks < 4; ks++) {
                    uint32_t bv[4];
                    int row = 16 * ks + (g8 & 1) * 8 + r8;
                    int unit = 2 * tp + (g8 >> 1);
                    LDSM4T(bv[0], bv[1], bv[2], bv[3],
                           Vb + row * 128 + ((unit ^ (row & 7)) << 4));
                    #pragma unroll
                    for (int rb = 0; rb < 2; rb++) {
                        mma_f16(o[rb][2 * tp], pa[ks][rb], &bv[0]);
                        mma_f16(o[rb][2 * tp + 1], pa[ks][rb], &bv[2]);
                    }
                }
            }
        }
    }

    #pragma unroll
    for (int rb = 0; rb < 2; rb++) {
        const float i0 = 1.f / lrow[rb][0], i1 = 1.f / lrow[rb][2];
        const int rlo = q0 + wid * 32 + rb * 16 + gr;
        __half* y0 = y + (size_t)(b * SEQ + rlo) * N_EMBD + h * HS;
        __half* y1 = y + (size_t)(b * SEQ + rlo + 8) * N_EMBD + h * HS;
        #pragma unroll
        for (int t = 0; t < 8; t++) {
            *(__half2*)(y0 + 8 * t + 2 * gc) =
                __floats2half2_rn(o[rb][t][0] * i0, o[rb][t][1] * i0);
            *(__half2*)(y1 + 8 * t + 2 * gc) =
                __floats2half2_rn(o[rb][t][2] * i1, o[rb][t][3] * i1);
        }
    }
}

// ---------------------------------------------------------------------------
extern "C" void kernel_launch(void* const* d_in, const int* in_sizes, int n_in,
                              void* d_out, int out_size)
{
    const float* x      = (const float*)d_in[0];
    const float* w_attn = (const float*)d_in[1];
    const float* w_proj = (const float*)d_in[2];
    float* out = (float*)d_out;

    __half *xh, *qkvh, *yh, *wta, *wtp;
    cudaGetSymbolAddress((void**)&xh, g_xh);
    cudaGetSymbolAddress((void**)&qkvh, g_qkvh);
    cudaGetSymbolAddress((void**)&yh, g_yh);
    cudaGetSymbolAddress((void**)&wta, g_wta_h);
    cudaGetSymbolAddress((void**)&wtp, g_wtp_h);

    cudaFuncSetAttribute(gemm_f16<true>, cudaFuncAttributeMaxDynamicSharedMemorySize, GEMM_SMEM);
    cudaFuncSetAttribute(gemm_f16<false>, cudaFuncAttributeMaxDynamicSharedMemorySize, GEMM_SMEM);
    cudaFuncSetAttribute(flash_f16, cudaFuncAttributeMaxDynamicSharedMemorySize, FLASH_SMEM);

    const int n4 = MTOT * N_EMBD / 4;
    cvt_half4<<<n4 / 256, 256>>>((const float4*)x, (__half2*)xh, n4);
    transpose_cvt<<<dim3(3 * N_EMBD / 32, N_EMBD / 32), 256>>>(w_attn, wta, N_EMBD, 3 * N_EMBD);
    transpose_cvt<<<dim3(N_EMBD / 32, N_EMBD / 32), 256>>>(w_proj, wtp, N_EMBD, N_EMBD);

    gemm_f16<true><<<dim3(3 * N_EMBD / 128, MTOT / 128), 128, GEMM_SMEM>>>(
        xh, wta, qkvh, MTOT, 3 * N_EMBD, N_EMBD, 1);

    flash_f16<<<dim3(SEQ / 128, BATCH * N_HEAD), 128, FLASH_SMEM>>>(qkvh, yh);

    gemm_f16<false><<<dim3(N_EMBD / 128, MTOT / 128), 128, GEMM_SMEM>>>(
        yh, wtp, out, MTOT, N_EMBD, N_EMBD, 0);
}

// round 17
// speedup vs baseline: 1.0237x; 1.0237x over previous
// R17: GEMMs reverted to R15 256-thread config (R16's 4-warp variant measured
// worse; 64% tensor is the HMMA-f32acc ceiling, not a bubble). All three prep
// kernels fused into one launch (identical per-element math).
#include <cuda_runtime.h>
#include <cuda_fp16.h>
#include <math.h>
#include <stdint.h>

#define N_EMBD 1024
#define N_HEAD 16
#define HS 64
#define BATCH 4
#define SEQ 2048
#define MTOT (BATCH * SEQ)

__device__ __half g_xh[(size_t)MTOT * N_EMBD];
__device__ __half g_qkvh[(size_t)MTOT * 3 * N_EMBD];
__device__ __half g_yh[(size_t)MTOT * N_EMBD];
__device__ __half g_wta_h[(size_t)3 * N_EMBD * N_EMBD];
__device__ __half g_wtp_h[(size_t)N_EMBD * N_EMBD];

// ---------------------------------------------------------------------------
__device__ __forceinline__ void cp_async16(uint32_t dst, const void* src) {
    asm volatile("cp.async.cg.shared.global [%0], [%1], 16;" :: "r"(dst), "l"(src));
}
#define CP_COMMIT() asm volatile("cp.async.commit_group;" ::: "memory")
#define CP_WAIT0() asm volatile("cp.async.wait_group 0;" ::: "memory")
#define CP_WAIT1() asm volatile("cp.async.wait_group 1;" ::: "memory")

#define LDSM4(r0, r1, r2, r3, addr) \
    asm volatile("ldmatrix.sync.aligned.m8n8.x4.shared.b16 {%0,%1,%2,%3}, [%4];" \
                 : "=r"(r0), "=r"(r1), "=r"(r2), "=r"(r3) : "r"(addr))
#define LDSM4T(r0, r1, r2, r3, addr) \
    asm volatile("ldmatrix.sync.aligned.m8n8.x4.trans.shared.b16 {%0,%1,%2,%3}, [%4];" \
                 : "=r"(r0), "=r"(r1), "=r"(r2), "=r"(r3) : "r"(addr))

__device__ __forceinline__ void mma_f16(float* c, const uint32_t* a, const uint32_t* b) {
    asm volatile(
        "mma.sync.aligned.m16n8k16.row.col.f32.f16.f16.f32 "
        "{%0,%1,%2,%3}, {%4,%5,%6,%7}, {%8,%9}, {%0,%1,%2,%3};"
        : "+f"(c[0]), "+f"(c[1]), "+f"(c[2]), "+f"(c[3])
        : "r"(a[0]), "r"(a[1]), "r"(a[2]), "r"(a[3]), "r"(b[0]), "r"(b[1]));
}

__device__ __forceinline__ uint32_t pack_h2(float a, float b) {
    __half2 h = __floats2half2_rn(a, b);
    return *reinterpret_cast<uint32_t*>(&h);
}
__device__ __forceinline__ float ex2f(float x) {
    float r;
    asm("ex2.approx.f32 %0, %1;" : "=f"(r) : "f"(x));
    return r;
}
__device__ __forceinline__ uint32_t ex2_h2(uint32_t d) {
    uint32_t r;
    asm("ex2.approx.f16x2 %0, %1;" : "=r"(r) : "r"(d));
    return r;
}

// ---------------------------------------------------------------------------
// Fused prep: one launch.
//   blocks [0, NB_CVT)                 : x fp32 -> fp16 (float4 granularity)
//   blocks [NB_CVT, NB_CVT+NB_TA)     : transpose+cvt w_attn  (96 x 32 tiles)
//   blocks [.., +NB_TP)               : transpose+cvt w_proj  (32 x 32 tiles)
// ---------------------------------------------------------------------------
#define N4_CVT (MTOT * N_EMBD / 4)         // 2,097,152 float4
#define NB_CVT (N4_CVT / 256)              // 8192 blocks
#define NB_TA  ((3 * N_EMBD / 32) * (N_EMBD / 32))   // 3072
#define NB_TP  ((N_EMBD / 32) * (N_EMBD / 32))       // 1024

__global__ __launch_bounds__(256) void prep_fused(
    const float* __restrict__ x, const float* __restrict__ w_attn,
    const float* __restrict__ w_proj)
{
    __shared__ float t[32][33];
    const int bid = blockIdx.x;
    if (bid < NB_CVT) {
        const int i = bid * 256 + threadIdx.x;
        float4 v = ((const float4*)x)[i];
        ((__half2*)g_xh)[2 * i] = __floats2half2_rn(v.x, v.y);
        ((__half2*)g_xh)[2 * i + 1] = __floats2half2_rn(v.z, v.w);
        return;
    }
    const float* in;
    __half* out;
    int R, C, tb;
    if (bid < NB_CVT + NB_TA) {
        tb = bid - NB_CVT;  in = w_attn;  out = g_wta_h;  R = N_EMBD;  C = 3 * N_EMBD;
    } else {
        tb = bid - NB_CVT - NB_TA;  in = w_proj;  out = g_wtp_h;  R = N_EMBD;  C = N_EMBD;
    }
    const int nbx = C / 32;
    const int bx = (tb % nbx) * 32, by = (tb / nbx) * 32;
    const int tx = threadIdx.x & 31, ty = threadIdx.x >> 5;
    #pragma unroll
    for (int i = ty; i < 32; i += 8)
        t[i][tx] = in[(size_t)(by + i) * C + bx + tx];
    __syncthreads();
    #pragma unroll
    for (int i = ty; i < 32; i += 8)
        out[(size_t)(bx + i) * R + by + tx] = __float2half_rn(t[tx][i]);
}

// ---------------------------------------------------------------------------
// fp16 GEMM (R15/R6 structure: 256 threads, 8 warps 2x4, 2-stage cp.async).
// ---------------------------------------------------------------------------
#define GEMM_SMEM 65536
#define QSCALE (0.125f * 1.4426950408889634f)

template <bool HALF_OUT>
__global__ __launch_bounds__(256, 2) void gemm_f16(
    const __half* __restrict__ A, const __half* __restrict__ Bt,
    void* __restrict__ Cv, int M, int N, int K, int scaleQ)
{
    extern __shared__ char smc[];
    const uint32_t sb = (uint32_t)__cvta_generic_to_shared(smc);
    const int tid = threadIdx.x, wid = tid >> 5, lane = tid & 31;
    const int gr = lane >> 2, gc = lane & 3;
    const int g8 = lane >> 3, r8 = lane & 7;
    const int wm = (wid & 1) * 64, wn = (wid >> 1) * 32;

    const __half* Ag = A + (size_t)blockIdx.y * 128 * K;
    const __half* Bg = Bt + (size_t)blockIdx.x * 128 * K;

    float acc[4][4][4];
    #pragma unroll
    for (int i = 0; i < 4; i++)
        #pragma unroll
        for (int j = 0; j < 4; j++)
            #pragma unroll
            for (int r = 0; r < 4; r++) acc[i][j][r] = 0.f;

    auto issue = [&](int c) {
        const int p = c & 1, k0 = c * 64;
        const uint32_t aB = sb + p * 32768, bB = aB + 16384;
        #pragma unroll
        for (int i = 0; i < 4; i++) {
            int u = tid + 256 * i, r = u >> 3, cu = u & 7;
            uint32_t d = (uint32_t)(r * 128 + ((cu ^ (r & 7)) << 4));
            cp_async16(aB + d, Ag + (size_t)r * K + k0 + cu * 8);
            cp_async16(bB + d, Bg + (size_t)r * K + k0 + cu * 8);
        }
        CP_COMMIT();
    };

    issue(0);
    const int NCH = K / 64;
    for (int c = 0; c < NCH; c++) {
        const int p = c & 1;
        if (c + 1 < NCH) { issue(c + 1); CP_WAIT1(); } else { CP_WAIT0(); }
        __syncthreads();
        const uint32_t aB = sb + p * 32768, bB = aB + 16384;

        #pragma unroll
        for (int ks = 0; ks < 4; ks++) {
            uint32_t a[4][4], b[4][2];
            #pragma unroll
            for (int i = 0; i < 4; i++) {
                int row = wm + i * 16 + (g8 & 1) * 8 + r8;
                int unit = 2 * ks + (g8 >> 1);
                LDSM4(a[i][0], a[i][1], a[i][2], a[i][3],
                      aB + row * 128 + ((unit ^ (row & 7)) << 4));
            }
            #pragma unroll
            for (int jp = 0; jp < 2; jp++) {
                int row = wn + jp * 16 + (g8 >> 1) * 8 + r8;
                int unit = 2 * ks + (g8 & 1);
                LDSM4(b[2 * jp][0], b[2 * jp][1], b[2 * jp + 1][0], b[2 * jp + 1][1],
                      bB + row * 128 + ((unit ^ (row & 7)) << 4));
            }
            #pragma unroll
            for (int i = 0; i < 4; i++)
                #pragma unroll
                for (int j = 0; j < 4; j++)
                    mma_f16(acc[i][j], a[i], b[j]);
        }
        __syncthreads();
    }

    const float sc = (scaleQ && blockIdx.x < 8) ? QSCALE : 1.0f;
    if (HALF_OUT) {
        __half* Ch = (__half*)Cv + (size_t)(blockIdx.y * 128 + wm) * N + blockIdx.x * 128 + wn;
        #pragma unroll
        for (int i = 0; i < 4; i++)
            #pragma unroll
            for (int j = 0; j < 4; j++) {
                *(__half2*)(Ch + (size_t)(i * 16 + gr) * N + j * 8 + 2 * gc) =
                    __floats2half2_rn(acc[i][j][0] * sc, acc[i][j][1] * sc);
                *(__half2*)(Ch + (size_t)(i * 16 + gr + 8) * N + j * 8 + 2 * gc) =
                    __floats2half2_rn(acc[i][j][2] * sc, acc[i][j][3] * sc);
            }
    } else {
        float* Cf = (float*)Cv + (size_t)(blockIdx.y * 128 + wm) * N + blockIdx.x * 128 + wn;
        #pragma unroll
        for (int i = 0; i < 4; i++)
            #pragma unroll
            for (int j = 0; j < 4; j++) {
                *(float2*)(Cf + (size_t)(i * 16 + gr) * N + j * 8 + 2 * gc) =
                    make_float2(acc[i][j][0], acc[i][j][1]);
                *(float2*)(Cf + (size_t)(i * 16 + gr + 8) * N + j * 8 + 2 * gc) =
                    make_float2(acc[i][j][2], acc[i][j][3]);
            }
    }
}

// ---------------------------------------------------------------------------
// fp16 flash attention (causal): unchanged from R15.
// ---------------------------------------------------------------------------
#define FQ_OFF 0
#define FK_OFF 16384
#define FV_OFF (16384 + 3 * 8192)
#define FLASH_SMEM 65536
#define MASKF (-60000.0f)

__global__ __launch_bounds__(128, 2) void flash_f16(
    const __half* __restrict__ qkv, __half* __restrict__ y)
{
    extern __shared__ char smc[];
    const uint32_t sb = (uint32_t)__cvta_generic_to_shared(smc);
    const int qt = gridDim.x - 1 - blockIdx.x;
    const int b = blockIdx.y >> 4, h = blockIdx.y & 15;
    const int tid = threadIdx.x, wid = tid >> 5, lane = tid & 31;
    const int gr = lane >> 2, gc = lane & 3;
    const int g8 = lane >> 3, r8 = lane & 7;
    const int C3 = 3 * N_EMBD;
    const int q0 = qt * 128;
    const __half* gb = qkv + (size_t)(b * SEQ) * C3 + h * HS;
    const int jmax = 2 * qt + 1;
    const int wrow = q0 + wid * 32;

    auto issue_kv = [&](int j) {
        const int p3 = j % 3, kb = j * 64;
        #pragma unroll
        for (int i = 0; i < 4; i++) {
            int u = tid + 128 * i, r = u >> 3, cu = u & 7;
            uint32_t d = (uint32_t)(r * 128 + ((cu ^ (r & 7)) << 4)) + p3 * 8192;
            cp_async16(sb + FK_OFF + d, gb + N_EMBD + (size_t)(kb + r) * C3 + cu * 8);
            cp_async16(sb + FV_OFF + d, gb + 2 * N_EMBD + (size_t)(kb + r) * C3 + cu * 8);
        }
        CP_COMMIT();
    };

    {
        #pragma unroll
        for (int i = 0; i < 8; i++) {
            int u = tid + 128 * i, r = u >> 3, cu = u & 7;
            cp_async16(sb + FQ_OFF + r * 128 + ((cu ^ (r & 7)) << 4),
                       gb + (size_t)(q0 + r) * C3 + cu * 8);
        }
        #pragma unroll
        for (int i = 0; i < 4; i++) {
            int u = tid + 128 * i, r = u >> 3, cu = u & 7;
            uint32_t d = (uint32_t)(r * 128 + ((cu ^ (r & 7)) << 4));
            cp_async16(sb + FK_OFF + d, gb + N_EMBD + (size_t)r * C3 + cu * 8);
            cp_async16(sb + FV_OFF + d, gb + 2 * N_EMBD + (size_t)r * C3 + cu * 8);
        }
        CP_COMMIT();
        issue_kv(1);
    }

    uint32_t qa[4][2][4];
    float o[2][8][4];
    #pragma unroll
    for (int rb = 0; rb < 2; rb++)
        #pragma unroll
        for (int t = 0; t < 8; t++)
            #pragma unroll
            for (int r = 0; r < 4; r++) o[rb][t][r] = 0.f;
    float lrow[2][4] = {{0.f, 0.f, 0.f, 0.f}, {0.f, 0.f, 0.f, 0.f}};
    float m[4] = {-1e30f, -1e30f, -1e30f, -1e30f};
    const uint32_t onesb[2] = {0x3C003C00u, 0x3C003C00u};

    for (int j = 0; j <= jmax; j++) {
        if (j == jmax) { CP_WAIT0(); } else { CP_WAIT1(); }
        __syncthreads();
        if (j + 2 <= jmax) issue_kv(j + 2);

        if (j == 0) {
            #pragma unroll
            for (int ks = 0; ks < 4; ks++)
                #pragma unroll
                for (int rb = 0; rb < 2; rb++) {
                    int row = wid * 32 + rb * 16 + (g8 & 1) * 8 + r8;
                    int unit = 2 * ks + (g8 >> 1);
                    LDSM4(qa[ks][rb][0], qa[ks][rb][1], qa[ks][rb][2], qa[ks][rb][3],
                          sb + FQ_OFF + row * 128 + ((unit ^ (row & 7)) << 4));
                }
        }

        const int p3 = j % 3, kb = j * 64;
        if (kb <= wrow + 31) {
            const uint32_t Kb = sb + FK_OFF + p3 * 8192;
            float s[8][2][4];
            #pragma unroll
            for (int t = 0; t < 8; t++)
                #pragma unroll
                for (int rb = 0; rb < 2; rb++)
                    #pragma unroll
                    for (int r = 0; r < 4; r++) s[t][rb][r] = 0.f;
            #pragma unroll
            for (int t = 0; t < 8; t++) {
                uint32_t bfr[8];
                #pragma unroll
                for (int kp = 0; kp < 2; kp++) {
                    int row = 8 * t + r8;
                    int unit = 4 * kp + g8;
                    LDSM4(bfr[4 * kp], bfr[4 * kp + 1], bfr[4 * kp + 2], bfr[4 * kp + 3],
                          Kb + row * 128 + ((unit ^ (row & 7)) << 4));
                }
                #pragma unroll
                for (int ks = 0; ks < 4; ks++)
                    #pragma unroll
                    for (int rb = 0; rb < 2; rb++)
                        mma_f16(s[t][rb], qa[ks][rb], &bfr[2 * ks]);
            }
            float tm[4] = {-1e30f, -1e30f, -1e30f, -1e30f};
            if (kb + 63 < wrow) {
                #pragma unroll
                for (int t = 0; t < 8; t++)
                    #pragma unroll
                    for (int rb = 0; rb < 2; rb++) {
                        tm[2 * rb]     = fmaxf(tm[2 * rb], fmaxf(s[t][rb][0], s[t][rb][1]));
                        tm[2 * rb + 1] = fmaxf(tm[2 * rb + 1], fmaxf(s[t][rb][2], s[t][rb][3]));
                    }
            } else {
                #pragma unroll
                for (int t = 0; t < 8; t++) {
                    const int c0 = kb + 8 * t + 2 * gc, c1 = c0 + 1;
                    #pragma unroll
                    for (int rb = 0; rb < 2; rb++) {
                        const int rlo = wrow + rb * 16 + gr, rhi = rlo + 8;
                        s[t][rb][0] = (c0 <= rlo) ? s[t][rb][0] : MASKF;
                        s[t][rb][1] = (c1 <= rlo) ? s[t][rb][1] : MASKF;
                        s[t][rb][2] = (c0 <= rhi) ? s[t][rb][2] : MASKF;
                        s[t][rb][3] = (c1 <= rhi) ? s[t][rb][3] : MASKF;
                        tm[2 * rb]     = fmaxf(tm[2 * rb], fmaxf(s[t][rb][0], s[t][rb][1]));
                        tm[2 * rb + 1] = fmaxf(tm[2 * rb + 1], fmaxf(s[t][rb][2], s[t][rb][3]));
                    }
                }
            }
            #pragma unroll
            for (int k = 0; k < 4; k++)
                #pragma unroll
                for (int off = 1; off <= 2; off <<= 1)
                    tm[k] = fmaxf(tm[k], __shfl_xor_sync(0xffffffffu, tm[k], off));
            float mn[4], cf[4];
            #pragma unroll
            for (int k = 0; k < 4; k++) {
                mn[k] = fmaxf(m[k], tm[k]);
                cf[k] = ex2f(m[k] - mn[k]);
                m[k] = mn[k];
            }
            uint32_t pa[4][2][4];
            #pragma unroll
            for (int t = 0; t < 8; t++) {
                const int ks = t >> 1, hi = (t & 1) * 2;
                #pragma unroll
                for (int rb = 0; rb < 2; rb++) {
                    pa[ks][rb][hi]     = ex2_h2(pack_h2(s[t][rb][0] - mn[2 * rb],
                                                        s[t][rb][1] - mn[2 * rb]));
                    pa[ks][rb][hi + 1] = ex2_h2(pack_h2(s[t][rb][2] - mn[2 * rb + 1],
                                                        s[t][rb][3] - mn[2 * rb + 1]));
                }
            }
            #pragma unroll
            for (int rb = 0; rb < 2; rb++) {
                lrow[rb][0] *= cf[2 * rb];     lrow[rb][1] *= cf[2 * rb];
                lrow[rb][2] *= cf[2 * rb + 1]; lrow[rb][3] *= cf[2 * rb + 1];
                #pragma unroll
                for (int t = 0; t < 8; t++) {
                    o[rb][t][0] *= cf[2 * rb];     o[rb][t][1] *= cf[2 * rb];
                    o[rb][t][2] *= cf[2 * rb + 1]; o[rb][t][3] *= cf[2 * rb + 1];
                }
            }
            #pragma unroll
            for (int ks = 0; ks < 4; ks++)
                #pragma unroll
                for (int rb = 0; rb < 2; rb++)
                    mma_f16(lrow[rb], pa[ks][rb], onesb);
            const uint32_t Vb = sb + FV_OFF + p3 * 8192;
            #pragma unroll
            for (int tp = 0; tp < 4; tp++) {
                #pragma unroll
                for (int ks = 0; ks < 4; ks++) {
                    uint32_t bv[4];
                    int row = 16 * ks + (g8 & 1) * 8 + r8;
                    int unit = 2 * tp + (g8 >> 1);
                    LDSM4T(bv[0], bv[1], bv[2], bv[3],
                           Vb + row * 128 + ((unit ^ (row & 7)) << 4));
                    #pragma unroll
                    for (int rb = 0; rb < 2; rb++) {
                        mma_f16(o[rb][2 * tp], pa[ks][rb], &bv[0]);
                        mma_f16(o[rb][2 * tp + 1], pa[ks][rb], &bv[2]);
                    }
                }
            }
        }
    }

    #pragma unroll
    for (int rb = 0; rb < 2; rb++) {
        const float i0 = 1.f / lrow[rb][0], i1 = 1.f / lrow[rb][2];
        const int rlo = q0 + wid * 32 + rb * 16 + gr;
        __half* y0 = y + (size_t)(b * SEQ + rlo) * N_EMBD + h * HS;
        __half* y1 = y + (size_t)(b * SEQ + rlo + 8) * N_EMBD + h * HS;
        #pragma unroll
        for (int t = 0; t < 8; t++) {
            *(__half2*)(y0 + 8 * t + 2 * gc) =
                __floats2half2_rn(o[rb][t][0] * i0, o[rb][t][1] * i0);
            *(__half2*)(y1 + 8 * t + 2 * gc) =
                __floats2half2_rn(o[rb][t][2] * i1, o[rb][t][3] * i1);
        }
    }
}

// ---------------------------------------------------------------------------
extern "C" void kernel_launch(void* const* d_in, const int* in_sizes, int n_in,
                              void* d_out, int out_size)
{
    const float* x      = (const float*)d_in[0];
    const float* w_attn = (const float*)d_in[1];
    const float* w_proj = (const float*)d_in[2];
    float* out = (float*)d_out;

    __half *xh, *qkvh, *yh, *wta, *wtp;
    cudaGetSymbolAddress((void**)&xh, g_xh);
    cudaGetSymbolAddress((void**)&qkvh, g_qkvh);
    cudaGetSymbolAddress((void**)&yh, g_yh);
    cudaGetSymbolAddress((void**)&wta, g_wta_h);
    cudaGetSymbolAddress((void**)&wtp, g_wtp_h);

    cudaFuncSetAttribute(gemm_f16<true>, cudaFuncAttributeMaxDynamicSharedMemorySize, GEMM_SMEM);
    cudaFuncSetAttribute(gemm_f16<false>, cudaFuncAttributeMaxDynamicSharedMemorySize, GEMM_SMEM);
    cudaFuncSetAttribute(flash_f16, cudaFuncAttributeMaxDynamicSharedMemorySize, FLASH_SMEM);

    // fused prep: cvt x + transpose/cvt both weights, one launch
    prep_fused<<<NB_CVT + NB_TA + NB_TP, 256>>>(x, w_attn, w_proj);

    gemm_f16<true><<<dim3(3 * N_EMBD / 128, MTOT / 128), 256, GEMM_SMEM>>>(
        xh, wta, qkvh, MTOT, 3 * N_EMBD, N_EMBD, 1);

    flash_f16<<<dim3(SEQ / 128, BATCH * N_HEAD), 128, FLASH_SMEM>>>(qkvh, yh);

    gemm_f16<false><<<dim3(N_EMBD / 128, MTOT / 128), 256, GEMM_SMEM>>>(
        yh, wtp, out, MTOT, N_EMBD, N_EMBD, 0);
}